// round 14
// baseline (speedup 1.0000x reference)
#include <cuda_runtime.h>
#include <cuda_bf16.h>
#include <math.h>
#include <stdint.h>

#define HDIM 1024
#define BDIM 128
#define TDIM 128
#define G3   (3 * HDIM)
#define BH   (BDIM * HDIM)

// Wi8: per-GRU packed W_hh int8 B-fragments:
// [which][bx][c(32)][gate(3)][lane(32)] uint4 {bh0,bh1,bl0,bl1} (48KB per block slab)
#define WI8_PER (32 * 3 * 32)                 // uint4 per block slab = 3072
// HfW: h in int8 A-fragment planes, u32 words:
// [par(2)][hi: 32768 u32][lo: 32768 u32]; word = ((c*8+w)*32+lane)*4+reg
#define HFW_U32 (2 * 65536)

// ----------------------------- scratch (device globals) ----------------------
__device__ float g_gates_p[(size_t)BDIM * TDIM * G3];
__device__ float g_gates_h[(size_t)BDIM * TDIM * G3];
__device__ float g_op[(size_t)TDIM * BDIM * HDIM];      // premise h, [T,B,H]
__device__ float g_hbuf[BH];                            // final hypothesis h
__device__ uint4 g_Wi8[(size_t)2 * 128 * WI8_PER];
__device__ uint32_t g_Hfw[HFW_U32];
__device__ float g_WyT[HDIM * HDIM];
__device__ float g_WyM[(size_t)TDIM * BDIM * HDIM];
__device__ float g_Wh[BH];
__device__ float g_r[BH];
__device__ float g_G1[BH];
__device__ float g_G2[BH];
__device__ float g_hstar[BH];

__device__ unsigned g_arrive  = 0;
__device__ unsigned g_release = 0;

__device__ __forceinline__ float sigmoidf_(float x) { return 1.0f / (1.0f + expf(-x)); }

__device__ __forceinline__ uint32_t f2tf32(float x) {
    uint32_t r;
    asm("cvt.rna.tf32.f32 %0, %1;" : "=r"(r) : "f"(x));
    return r;
}

__device__ __forceinline__ void mma_tf32(float* d, const uint32_t* a, const uint32_t* b) {
    asm("mma.sync.aligned.m16n8k8.row.col.f32.tf32.tf32.f32 "
        "{%0,%1,%2,%3},{%4,%5,%6,%7},{%8,%9},{%0,%1,%2,%3};"
        : "+f"(d[0]), "+f"(d[1]), "+f"(d[2]), "+f"(d[3])
        : "r"(a[0]), "r"(a[1]), "r"(a[2]), "r"(a[3]), "r"(b[0]), "r"(b[1]));
}

// int8 m16n8k32 mma variants (s32 accum)
#define DEF_IMMA(NAME, AT, BT)                                                  \
__device__ __forceinline__ void NAME(int* d, const uint32_t* a,                 \
                                     uint32_t b0, uint32_t b1) {                \
    asm("mma.sync.aligned.m16n8k32.row.col.s32." AT "." BT ".s32 "              \
        "{%0,%1,%2,%3},{%4,%5,%6,%7},{%8,%9},{%0,%1,%2,%3};"                    \
        : "+r"(d[0]), "+r"(d[1]), "+r"(d[2]), "+r"(d[3])                        \
        : "r"(a[0]), "r"(a[1]), "r"(a[2]), "r"(a[3]), "r"(b0), "r"(b1));        \
}
DEF_IMMA(mma_s8s8, "s8", "s8")
DEF_IMMA(mma_s8u8, "s8", "u8")
DEF_IMMA(mma_u8s8, "u8", "s8")
DEF_IMMA(mma_u8u8, "u8", "u8")

// ----------------------------- pack W_hh into int8 B-fragment layout ---------
// idx = [which][bx][c][gate][lane]; uint4 = {bh0,bh1,bl0,bl1}
// b0: gate-row (lane>>2), k = c*32 + 4*(lane&3)+j ; b1: k+16
__global__ void pack_w_i8(const float* __restrict__ Wp, const float* __restrict__ Whh_h,
                          uint4* __restrict__ out)
{
    int idx = blockIdx.x * blockDim.x + threadIdx.x;
    if (idx >= 2 * 128 * WI8_PER) return;
    int lane = idx & 31;
    int gate = (idx >> 5) % 3;
    int c    = (idx / 96) & 31;
    int bx   = (idx / (96 * 32)) & 127;
    int which = idx / (96 * 32 * 128);
    const float* W = which ? Whh_h : Wp;
    const float* row = W + (size_t)(gate * HDIM + bx * 8 + (lane >> 2)) * HDIM
                         + c * 32 + 4 * (lane & 3);

    uint32_t bh[2] = {0, 0}, bl[2] = {0, 0};
#pragma unroll
    for (int half = 0; half < 2; half++) {
#pragma unroll
        for (int j = 0; j < 4; j++) {
            float v = row[half * 16 + j];
            int wq = __float2int_rn(v * (32767.0f * 32.0f));
            wq = max(-32767, min(32767, wq));
            uint32_t hi = (uint32_t)((wq >> 8) & 0xFF);
            uint32_t lo = (uint32_t)(wq & 0xFF);
            bh[half] |= hi << (8 * j);
            bl[half] |= lo << (8 * j);
        }
    }
    uint4 o;
    o.x = bh[0]; o.y = bh[1]; o.z = bl[0]; o.w = bl[1];
    out[idx] = o;
}

__global__ void transpose1024(const float* __restrict__ in, float* __restrict__ out)
{
    __shared__ float t[32][33];
    int x = blockIdx.x * 32 + threadIdx.x;
    int y0 = blockIdx.y * 32;
    for (int r = threadIdx.y; r < 32; r += 8)
        t[r][threadIdx.x] = in[(size_t)(y0 + r) * HDIM + x];
    __syncthreads();
    int xo = blockIdx.y * 32 + threadIdx.x;
    for (int r = threadIdx.y; r < 32; r += 8)
        out[(size_t)(blockIdx.x * 32 + r) * HDIM + xo] = t[threadIdx.x][r];
}

// ----------------------------- tf32 mma GEMM (unchanged, proven) -------------
template <bool BIAS>
__global__ void __launch_bounds__(256) gemm_tf32(
    const float* __restrict__ A, const float* __restrict__ Bw,
    const float* __restrict__ bias, float* __restrict__ C,
    int M, int N, int K)
{
    __shared__ uint32_t As[32][132];
    __shared__ uint32_t Bs[32][132];

    const int tid = threadIdx.x;
    const int lane = tid & 31, wid = tid >> 5;
    const int g = lane >> 2, tg = lane & 3;
    const int wm = (wid & 3) * 32;
    const int wn = (wid >> 2) * 64;
    const int m0 = blockIdx.y * 128, n0 = blockIdx.x * 128;

    float acc[2][8][4];
#pragma unroll
    for (int a = 0; a < 2; a++)
#pragma unroll
        for (int b = 0; b < 8; b++)
#pragma unroll
            for (int c = 0; c < 4; c++) acc[a][b][c] = 0.f;

    for (int k0 = 0; k0 < K; k0 += 32) {
#pragma unroll
        for (int r = 0; r < 4; r++) {
            int idx = tid + r * 256;
            int row = idx >> 3, kq = (idx & 7) * 4;
            float4 av = *(const float4*)&A[(size_t)(m0 + row) * K + k0 + kq];
            As[kq + 0][row] = f2tf32(av.x);
            As[kq + 1][row] = f2tf32(av.y);
            As[kq + 2][row] = f2tf32(av.z);
            As[kq + 3][row] = f2tf32(av.w);
            float4 bv = *(const float4*)&Bw[(size_t)(n0 + row) * K + k0 + kq];
            Bs[kq + 0][row] = f2tf32(bv.x);
            Bs[kq + 1][row] = f2tf32(bv.y);
            Bs[kq + 2][row] = f2tf32(bv.z);
            Bs[kq + 3][row] = f2tf32(bv.w);
        }
        __syncthreads();
#pragma unroll
        for (int kk = 0; kk < 32; kk += 8) {
            uint32_t af[2][4], bf[8][2];
#pragma unroll
            for (int mt = 0; mt < 2; mt++) {
                af[mt][0] = As[kk + tg][wm + mt * 16 + g];
                af[mt][1] = As[kk + tg][wm + mt * 16 + g + 8];
                af[mt][2] = As[kk + tg + 4][wm + mt * 16 + g];
                af[mt][3] = As[kk + tg + 4][wm + mt * 16 + g + 8];
            }
#pragma unroll
            for (int nt = 0; nt < 8; nt++) {
                bf[nt][0] = Bs[kk + tg][wn + nt * 8 + g];
                bf[nt][1] = Bs[kk + tg + 4][wn + nt * 8 + g];
            }
#pragma unroll
            for (int mt = 0; mt < 2; mt++)
#pragma unroll
                for (int nt = 0; nt < 8; nt++)
                    mma_tf32(acc[mt][nt], af[mt], bf[nt]);
        }
        __syncthreads();
    }

#pragma unroll
    for (int mt = 0; mt < 2; mt++) {
#pragma unroll
        for (int nt = 0; nt < 8; nt++) {
            int row = m0 + wm + mt * 16 + g;
            int col = n0 + wn + nt * 8 + 2 * tg;
            float b0 = BIAS ? bias[col] : 0.f;
            float b1 = BIAS ? bias[col + 1] : 0.f;
            C[(size_t)row * N + col]       = acc[mt][nt][0] + b0;
            C[(size_t)row * N + col + 1]   = acc[mt][nt][1] + b1;
            C[(size_t)(row + 8) * N + col]     = acc[mt][nt][2] + b0;
            C[(size_t)(row + 8) * N + col + 1] = acc[mt][nt][3] + b1;
        }
    }
}

// ----------------------------- persistent GRU scan (int8 IMMA) ---------------
// 128 blocks x 256 thr (8 warps, M-split: warp w = batches 16w..16w+15, full K).
// h quantized to int16 (|h|<1), split s8-hi/u8-lo planes; W int16 (|W|<=1/32)
// split likewise, resident in 48KB smem as B-fragments. 4 IMMAs reconstruct
// the exact int16xint16 product. A-fragments read by LDG.128, depth-4 ring.
#define SMEM_BYTES (WI8_PER * 16)   // 49152

__global__ void __launch_bounds__(256) gru_scan_i8(
    const float* __restrict__ gates_p, const float* __restrict__ gates_h,
    const uint4* __restrict__ Wi8,
    const float* __restrict__ pbhh, const float* __restrict__ hbhh,
    float* __restrict__ op, float* __restrict__ hbuf, uint32_t* __restrict__ HfW)
{
    extern __shared__ uint4 Wsm[];   // 3072 uint4

    const int tid = threadIdx.x, lane = tid & 31, wid = tid >> 5;
    const int g = lane >> 2, tg = lane & 3;
    const int bx = blockIdx.x;
    const int hc = bx * 8;

    const unsigned rel0 = *(volatile unsigned*)&g_release;

    // premise W slab -> smem
    {
        const uint4* src = Wi8 + (size_t)bx * WI8_PER;
        for (int i = tid; i < WI8_PER; i += 256) Wsm[i] = src[i];
    }
    __syncthreads();

    // thread owns cells: rows b_i = 16*wid+g+8i (i=0,1), cols hc+2tg+jj (jj=0,1)
    float hp[4] = {0.f, 0.f, 0.f, 0.f};
    float bR[2], bZ[2], bN[2];
    {
        int c0 = hc + 2 * tg;
        bR[0] = pbhh[c0];            bR[1] = pbhh[c0 + 1];
        bZ[0] = pbhh[HDIM + c0];     bZ[1] = pbhh[HDIM + c0 + 1];
        bN[0] = pbhh[2 * HDIM + c0]; bN[1] = pbhh[2 * HDIM + c0 + 1];
    }

    // producer u16 indices into A-fragment planes.
    // word q = (hc+2tg)>>2 = 2bx + (tg>>1); word = ((cq*8+w)*32 + (g*4+qt))*4 + i + 2*rh
    const int q   = 2 * bx + (tg >> 1);
    const int cq  = q >> 3, qt = q & 3, rh2 = (q >> 2) & 1;
    const uint32_t widx0 = (uint32_t)(((cq * 8 + wid) * 32 + (g * 4 + qt)) * 4 + 2 * rh2);
    const uint32_t o16_0 = widx0 * 2 + (tg & 1);        // i=0
    const uint32_t o16_1 = (widx0 + 1) * 2 + (tg & 1);  // i=1
    uint16_t* H16 = (uint16_t*)HfW;

    const float S = 1.0f / (32767.0f * 32767.0f * 32.0f);

    for (int s = 0; s < 256; s++) {
        const bool prem = s < 128;
        const int t = s & 127;

        if (s == 128) {
            const uint4* src = Wi8 + ((size_t)128 + bx) * WI8_PER;
            for (int i = tid; i < WI8_PER; i += 256) Wsm[i] = src[i];
            __syncthreads();
            int c0 = hc + 2 * tg;
            bR[0] = hbhh[c0];            bR[1] = hbhh[c0 + 1];
            bZ[0] = hbhh[HDIM + c0];     bZ[1] = hbhh[HDIM + c0 + 1];
            bN[0] = hbhh[2 * HDIM + c0]; bN[1] = hbhh[2 * HDIM + c0 + 1];
        }

        // gx prefetch (independent of h): cells (b_i, hc+2tg+jj)
        const float* gx = prem ? gates_p : gates_h;
        float gr[4], gz[4], gn[4];
#pragma unroll
        for (int i = 0; i < 2; i++) {
            int b = wid * 16 + g + 8 * i;
            const float* gxp = gx + ((size_t)b * TDIM + t) * G3 + hc + 2 * tg;
#pragma unroll
            for (int jj = 0; jj < 2; jj++) {
                gr[i * 2 + jj] = __ldg(&gxp[jj]);
                gz[i * 2 + jj] = __ldg(&gxp[HDIM + jj]);
                gn[i * 2 + jj] = __ldg(&gxp[2 * HDIM + jj]);
            }
        }

        int acc_hh[3][4], acc_mid[3][4], acc_ll[3][4];
#pragma unroll
        for (int gt = 0; gt < 3; gt++)
#pragma unroll
            for (int r = 0; r < 4; r++) {
                acc_hh[gt][r] = 0; acc_mid[gt][r] = 0; acc_ll[gt][r] = 0;
            }

        if (s > 0) {
            const uint4* Ahi = (const uint4*)(HfW + (size_t)((s - 1) & 1) * 65536);
            const uint4* Alo = Ahi + 8192;

            // depth-4 register ring of (hi,lo) fragment pairs
            uint4 rhb[4], rlb[4];
#pragma unroll
            for (int p = 0; p < 4; p++) {
                int fi = (p * 8 + wid) * 32 + lane;
                rhb[p] = __ldg(&Ahi[fi]);
                rlb[p] = __ldg(&Alo[fi]);
            }
#pragma unroll 4
            for (int c = 0; c < 32; c++) {
                const int slot = c & 3;
                uint4 ah = rhb[slot], al = rlb[slot];
                if (c + 4 < 32) {
                    int fi = ((c + 4) * 8 + wid) * 32 + lane;
                    rhb[slot] = __ldg(&Ahi[fi]);
                    rlb[slot] = __ldg(&Alo[fi]);
                }
#pragma unroll
                for (int gt = 0; gt < 3; gt++) {
                    uint4 wv = Wsm[(c * 3 + gt) * 32 + lane];
                    mma_s8s8(acc_hh[gt],  (const uint32_t*)&ah, wv.x, wv.y);
                    mma_s8u8(acc_mid[gt], (const uint32_t*)&ah, wv.z, wv.w);
                    mma_u8s8(acc_mid[gt], (const uint32_t*)&al, wv.x, wv.y);
                    mma_u8u8(acc_ll[gt],  (const uint32_t*)&al, wv.z, wv.w);
                }
            }
        }

        // epilogue: 4 cells; creg = i*2+jj matches accumulator layout
        const uint32_t par16 = (uint32_t)(s & 1) * 131072u;
#pragma unroll
        for (int i = 0; i < 2; i++) {
            int b = wid * 16 + g + 8 * i;
            float h2[2];
#pragma unroll
            for (int jj = 0; jj < 2; jj++) {
                int cr = i * 2 + jj;
                float d0 = S * (65536.0f * (float)acc_hh[0][cr] + 256.0f * (float)acc_mid[0][cr] + (float)acc_ll[0][cr]);
                float d1 = S * (65536.0f * (float)acc_hh[1][cr] + 256.0f * (float)acc_mid[1][cr] + (float)acc_ll[1][cr]);
                float d2 = S * (65536.0f * (float)acc_hh[2][cr] + 256.0f * (float)acc_mid[2][cr] + (float)acc_ll[2][cr]);
                float r = sigmoidf_(gr[cr] + d0 + bR[jj]);
                float z = sigmoidf_(gz[cr] + d1 + bZ[jj]);
                float n = tanhf(gn[cr] + r * (d2 + bN[jj]));
                float h = (1.f - z) * n + z * hp[cr];
                hp[cr] = h;
                h2[jj] = h;
            }
            // fp32 stores
            if (prem) {
                float2* dst = (float2*)(op + (size_t)t * BH + (size_t)b * HDIM + hc + 2 * tg);
                *dst = make_float2(h2[0], h2[1]);
            } else if (s == 255) {
                float2* dst = (float2*)(hbuf + (size_t)b * HDIM + hc + 2 * tg);
                *dst = make_float2(h2[0], h2[1]);
            }
            // int16 split -> u16 halfword stores into hi/lo planes
            int q0 = __float2int_rn(h2[0] * 32767.0f);
            int q1 = __float2int_rn(h2[1] * 32767.0f);
            uint16_t hi16 = (uint16_t)(((q0 >> 8) & 0xFF) | (((q1 >> 8) & 0xFF) << 8));
            uint16_t lo16 = (uint16_t)((q0 & 0xFF) | ((q1 & 0xFF) << 8));
            uint32_t o16 = par16 + (i ? o16_1 : o16_0);
            H16[o16]         = hi16;
            H16[o16 + 65536] = lo16;
        }

        // grid barrier (tight spin)
        __threadfence();
        __syncthreads();
        if (tid == 0) {
            unsigned r = atomicAdd(&g_arrive, 1u);
            if ((r & 127u) == 127u) atomicAdd(&g_release, 1u);
            while ((unsigned)(*(volatile unsigned*)&g_release - rel0) < (unsigned)(s + 1)) { }
            __threadfence();
        }
        __syncthreads();
    }
}

// ----------------------------- fp32 GEMM for small matmuls -------------------
template <bool TRANSB, bool BIAS>
__global__ void gemm_tiled(const float* __restrict__ A, const float* __restrict__ Bm,
                           const float* __restrict__ bias, float* __restrict__ C,
                           int M, int N, int K)
{
    __shared__ float As[8][132];
    __shared__ float Bs[8][132];

    const int tid = threadIdx.x;
    const int tx = tid & 15, ty = tid >> 4;
    const int m0 = blockIdx.y * 128, n0 = blockIdx.x * 128;

    float acc[8][8];
#pragma unroll
    for (int i = 0; i < 8; i++)
#pragma unroll
        for (int j = 0; j < 8; j++) acc[i][j] = 0.f;

    const int a_row = tid >> 1;
    const int a_k4  = (tid & 1) * 4;
    const int b_kr  = tid >> 5;
    const int b_n4  = (tid & 31) * 4;

    for (int k0 = 0; k0 < K; k0 += 8) {
        float4 av = *(const float4*)&A[(size_t)(m0 + a_row) * K + k0 + a_k4];
        As[a_k4 + 0][a_row] = av.x;
        As[a_k4 + 1][a_row] = av.y;
        As[a_k4 + 2][a_row] = av.z;
        As[a_k4 + 3][a_row] = av.w;
        if (TRANSB) {
            float4 bv = *(const float4*)&Bm[(size_t)(n0 + a_row) * K + k0 + a_k4];
            Bs[a_k4 + 0][a_row] = bv.x;
            Bs[a_k4 + 1][a_row] = bv.y;
            Bs[a_k4 + 2][a_row] = bv.z;
            Bs[a_k4 + 3][a_row] = bv.w;
        } else {
            float4 bv = *(const float4*)&Bm[(size_t)(k0 + b_kr) * N + n0 + b_n4];
            Bs[b_kr][b_n4 + 0] = bv.x;
            Bs[b_kr][b_n4 + 1] = bv.y;
            Bs[b_kr][b_n4 + 2] = bv.z;
            Bs[b_kr][b_n4 + 3] = bv.w;
        }
        __syncthreads();
#pragma unroll
        for (int kk = 0; kk < 8; kk++) {
            float a[8], b[8];
#pragma unroll
            for (int i = 0; i < 8; i++) a[i] = As[kk][ty + 16 * i];
#pragma unroll
            for (int j = 0; j < 8; j++) b[j] = Bs[kk][tx + 16 * j];
#pragma unroll
            for (int i = 0; i < 8; i++)
#pragma unroll
                for (int j = 0; j < 8; j++) acc[i][j] += a[i] * b[j];
        }
        __syncthreads();
    }

#pragma unroll
    for (int i = 0; i < 8; i++) {
        int m = m0 + ty + 16 * i;
#pragma unroll
        for (int j = 0; j < 8; j++) {
            int n = n0 + tx + 16 * j;
            float v = acc[i][j];
            if (BIAS) v += bias[n];
            C[(size_t)m * N + n] = v;
        }
    }
}

// ----------------------------- attention -------------------------------------
__global__ void attn_kernel(const float* __restrict__ WyM, const float* __restrict__ Wh,
                            const float* __restrict__ Walpha, const float* __restrict__ op,
                            float* __restrict__ rout)
{
    __shared__ float sc[128];
    __shared__ float red[256];
    const int b = blockIdx.x;
    const int tid = threadIdx.x;
    const int lane = tid & 31;
    const int warp = tid >> 5;

    for (int t = warp; t < TDIM; t += 8) {
        const float* wy = WyM + ((size_t)t * BDIM + b) * HDIM;
        const float* wh = Wh + (size_t)b * HDIM;
        float s = 0.f;
        for (int d = lane; d < HDIM; d += 32)
            s += tanhf(wy[d] + wh[d]) * Walpha[d];
#pragma unroll
        for (int o = 16; o > 0; o >>= 1) s += __shfl_xor_sync(0xffffffffu, s, o);
        if (lane == 0) sc[t] = s;
    }
    __syncthreads();

    float v = (tid < 128) ? sc[tid] : -INFINITY;
    red[tid] = v;
    __syncthreads();
    for (int s = 128; s > 0; s >>= 1) {
        if (tid < s) red[tid] = fmaxf(red[tid], red[tid + s]);
        __syncthreads();
    }
    float mx = red[0];
    __syncthreads();
    float e = (tid < 128) ? expf(sc[tid] - mx) : 0.f;
    red[tid] = e;
    __syncthreads();
    for (int s = 128; s > 0; s >>= 1) {
        if (tid < s) red[tid] += red[tid + s];
        __syncthreads();
    }
    float sum = red[0];
    __syncthreads();
    if (tid < 128) sc[tid] = e / sum;
    __syncthreads();

    for (int h = tid; h < HDIM; h += 256) {
        float acc = 0.f;
        for (int t = 0; t < TDIM; t++)
            acc += sc[t] * op[((size_t)t * BDIM + b) * HDIM + h];
        rout[(size_t)b * HDIM + h] = acc;
    }
}

__global__ void combine_tanh(const float* __restrict__ a, const float* __restrict__ b,
                             float* __restrict__ c, int n)
{
    int i = blockIdx.x * blockDim.x + threadIdx.x;
    if (i < n) c[i] = tanhf(a[i] + b[i]);
}

__global__ void final_kernel(const float* __restrict__ hstar, const float* __restrict__ outw,
                             const float* __restrict__ outb, float* __restrict__ out)
{
    __shared__ float red[128];
    __shared__ float lg[3];
    const int b = blockIdx.x;
    const int tid = threadIdx.x;

    for (int c = 0; c < 3; c++) {
        float p = 0.f;
        for (int h = tid; h < HDIM; h += 128)
            p += hstar[(size_t)b * HDIM + h] * outw[(size_t)c * HDIM + h];
        red[tid] = p;
        __syncthreads();
        for (int s = 64; s > 0; s >>= 1) {
            if (tid < s) red[tid] += red[tid + s];
            __syncthreads();
        }
        if (tid == 0) lg[c] = tanhf(red[0] + outb[c]);
        __syncthreads();
    }
    if (tid == 0) {
        float m = fmaxf(lg[0], fmaxf(lg[1], lg[2]));
        float s = expf(lg[0] - m) + expf(lg[1] - m) + expf(lg[2] - m);
        float lse = logf(s);
        for (int c = 0; c < 3; c++) out[b * 3 + c] = lg[c] - m - lse;
    }
}

// ----------------------------- launch ----------------------------------------
extern "C" void kernel_launch(void* const* d_in, const int* in_sizes, int n_in,
                              void* d_out, int out_size)
{
    const float* premise    = (const float*)d_in[0];
    const float* hypothesis = (const float*)d_in[1];
    const float* p_Wih = (const float*)d_in[2];
    const float* p_Whh = (const float*)d_in[3];
    const float* p_bih = (const float*)d_in[4];
    const float* p_bhh = (const float*)d_in[5];
    const float* h_Wih = (const float*)d_in[6];
    const float* h_Whh = (const float*)d_in[7];
    const float* h_bih = (const float*)d_in[8];
    const float* h_bhh = (const float*)d_in[9];
    const float* W_y     = (const float*)d_in[10];
    const float* W_h     = (const float*)d_in[11];
    const float* W_alpha = (const float*)d_in[12];
    const float* W_x     = (const float*)d_in[13];
    const float* W_p     = (const float*)d_in[14];
    const float* out_w   = (const float*)d_in[15];
    const float* out_b   = (const float*)d_in[16];

    float *gates_p, *gates_h, *op, *hbuf, *WyT, *WyM, *Whs, *rs, *G1, *G2, *hstar;
    uint4* Wi8;
    uint32_t* HfW;
    cudaGetSymbolAddress((void**)&gates_p, g_gates_p);
    cudaGetSymbolAddress((void**)&gates_h, g_gates_h);
    cudaGetSymbolAddress((void**)&op,      g_op);
    cudaGetSymbolAddress((void**)&hbuf,    g_hbuf);
    cudaGetSymbolAddress((void**)&Wi8,     g_Wi8);
    cudaGetSymbolAddress((void**)&HfW,     g_Hfw);
    cudaGetSymbolAddress((void**)&WyT,     g_WyT);
    cudaGetSymbolAddress((void**)&WyM,     g_WyM);
    cudaGetSymbolAddress((void**)&Whs,     g_Wh);
    cudaGetSymbolAddress((void**)&rs,      g_r);
    cudaGetSymbolAddress((void**)&G1,      g_G1);
    cudaGetSymbolAddress((void**)&G2,      g_G2);
    cudaGetSymbolAddress((void**)&hstar,   g_hstar);

    const int MB = TDIM * BDIM;

    // prep
    {
        int n = 2 * 128 * WI8_PER;
        pack_w_i8<<<(n + 255) / 256, 256>>>(p_Whh, h_Whh, Wi8);
    }
    transpose1024<<<dim3(32, 32), dim3(32, 8)>>>(W_y, WyT);

    // input-gate GEMMs
    gemm_tf32<true><<<dim3(G3 / 128, MB / 128), 256>>>(
        premise, p_Wih, p_bih, gates_p, MB, G3, HDIM);
    gemm_tf32<true><<<dim3(G3 / 128, MB / 128), 256>>>(
        hypothesis, h_Wih, h_bih, gates_h, MB, G3, HDIM);

    // persistent scan (int8 IMMA)
    static bool attr_set = false;
    if (!attr_set) {
        cudaFuncSetAttribute(gru_scan_i8,
                             cudaFuncAttributeMaxDynamicSharedMemorySize,
                             SMEM_BYTES);
        attr_set = true;
    }
    gru_scan_i8<<<128, 256, SMEM_BYTES>>>(
        gates_p, gates_h, Wi8, p_bhh, h_bhh, op, hbuf, HfW);

    // attention
    gemm_tf32<false><<<dim3(HDIM / 128, MB / 128), 256>>>(
        op, WyT, nullptr, WyM, MB, HDIM, HDIM);
    gemm_tiled<false, false><<<dim3(HDIM / 128, 1), 256>>>(
        hbuf, W_h, nullptr, Whs, BDIM, HDIM, HDIM);
    attn_kernel<<<128, 256>>>(WyM, Whs, W_alpha, op, rs);

    // h_star and classifier
    gemm_tiled<false, false><<<dim3(HDIM / 128, 1), 256>>>(
        rs, W_p, nullptr, G1, BDIM, HDIM, HDIM);
    gemm_tiled<false, false><<<dim3(HDIM / 128, 1), 256>>>(
        hbuf, W_x, nullptr, G2, BDIM, HDIM, HDIM);
    combine_tanh<<<(BH + 255) / 256, 256>>>(G1, G2, hstar, BH);
    final_kernel<<<128, 128>>>(hstar, out_w, out_b, (float*)d_out);
}

// round 15
// speedup vs baseline: 1.8761x; 1.8761x over previous
#include <cuda_runtime.h>
#include <cuda_bf16.h>
#include <cuda_fp16.h>
#include <math.h>
#include <stdint.h>

#define HDIM 1024
#define BDIM 128
#define TDIM 128
#define G3   (3 * HDIM)
#define BH   (BDIM * HDIM)

// Wf16: per-GRU packed W_hh fp16 B-fragments:
// [which][bx][c(64)][gate(3)][lane(32)] uint2 {B0,B1}  (48KB per block slab)
#define WF16_U2_PER 6144                      // uint2 per block slab
#define WF16_U4_PER 3072                      // same slab in uint4
// Hf (SoA per chunk): chunk c (k16) = 512 uint4: [wid][lane] hi (256) then lo (256)
#define HF_U4  (2 * 32768)

// ----------------------------- scratch (device globals) ----------------------
__device__ float g_gates_p[(size_t)BDIM * TDIM * G3];
__device__ float g_gates_h[(size_t)BDIM * TDIM * G3];
__device__ float g_op[(size_t)TDIM * BDIM * HDIM];      // premise h, [T,B,H]
__device__ float g_hbuf[BH];                            // final hypothesis h
__device__ uint4 g_Wf16[(size_t)2 * 128 * WF16_U4_PER];
__device__ uint4 g_Hf[HF_U4];
__device__ float g_WyT[HDIM * HDIM];
__device__ float g_WyM[(size_t)TDIM * BDIM * HDIM];
__device__ float g_Wh[BH];
__device__ float g_r[BH];
__device__ float g_G1[BH];
__device__ float g_G2[BH];
__device__ float g_hstar[BH];

__device__ unsigned g_arrive  = 0;
__device__ unsigned g_release = 0;

__device__ __forceinline__ float sigmoidf_(float x) { return 1.0f / (1.0f + expf(-x)); }

__device__ __forceinline__ uint32_t f2tf32(float x) {
    uint32_t r;
    asm("cvt.rna.tf32.f32 %0, %1;" : "=r"(r) : "f"(x));
    return r;
}

__device__ __forceinline__ void mma_tf32(float* d, const uint32_t* a, const uint32_t* b) {
    asm("mma.sync.aligned.m16n8k8.row.col.f32.tf32.tf32.f32 "
        "{%0,%1,%2,%3},{%4,%5,%6,%7},{%8,%9},{%0,%1,%2,%3};"
        : "+f"(d[0]), "+f"(d[1]), "+f"(d[2]), "+f"(d[3])
        : "r"(a[0]), "r"(a[1]), "r"(a[2]), "r"(a[3]), "r"(b[0]), "r"(b[1]));
}

__device__ __forceinline__ void mma_f16(float* d, const uint32_t* a, uint32_t b0, uint32_t b1) {
    asm("mma.sync.aligned.m16n8k16.row.col.f32.f16.f16.f32 "
        "{%0,%1,%2,%3},{%4,%5,%6,%7},{%8,%9},{%0,%1,%2,%3};"
        : "+f"(d[0]), "+f"(d[1]), "+f"(d[2]), "+f"(d[3])
        : "r"(a[0]), "r"(a[1]), "r"(a[2]), "r"(a[3]), "r"(b0), "r"(b1));
}

__device__ __forceinline__ uint32_t packh2(float a, float b) {
    __half2 h = __floats2half2_rn(a, b);
    return *(uint32_t*)&h;
}

// ---- mbarrier / bulk-copy helpers (proven R10) ------------------------------
__device__ __forceinline__ void mbar_init(uint32_t a, uint32_t cnt) {
    asm volatile("mbarrier.init.shared.b64 [%0], %1;" :: "r"(a), "r"(cnt) : "memory");
}
__device__ __forceinline__ void mbar_expect(uint32_t a, uint32_t tx) {
    asm volatile("mbarrier.arrive.expect_tx.shared.b64 _, [%0], %1;" :: "r"(a), "r"(tx) : "memory");
}
__device__ __forceinline__ void bulk_g2s(uint32_t dst, const void* src, uint32_t bytes, uint32_t mbar) {
    asm volatile("cp.async.bulk.shared::cta.global.mbarrier::complete_tx::bytes [%0], [%1], %2, [%3];"
                 :: "r"(dst), "l"(src), "r"(bytes), "r"(mbar) : "memory");
}
__device__ __forceinline__ void mbar_wait(uint32_t a, uint32_t parity) {
    asm volatile(
        "{\n\t.reg .pred P;\n"
        "WL_%=:\n\t"
        "mbarrier.try_wait.parity.shared.b64 P, [%0], %1;\n\t"
        "@P bra WD_%=;\n\t"
        "bra WL_%=;\n"
        "WD_%=:\n\t}"
        :: "r"(a), "r"(parity) : "memory");
}

// ----------------------------- pack W_hh into fp16 B-fragment layout ---------
// idx = [which][bx][c][gate][lane]; uint2 {B0 = (k=2tg,2tg+1), B1 = (k+8,k+9)}
__global__ void pack_w_f16(const float* __restrict__ Wp, const float* __restrict__ Whh_h,
                           uint2* __restrict__ out)
{
    int idx = blockIdx.x * blockDim.x + threadIdx.x;
    if (idx >= 2 * 128 * WF16_U2_PER) return;
    int lane = idx & 31;
    int gate = (idx >> 5) % 3;
    int c    = (idx / 96) & 63;
    int bx   = (idx / 6144) & 127;
    int which = idx / (6144 * 128);
    int g = lane >> 2, tg = lane & 3;
    const float* W = which ? Whh_h : Wp;
    const float* row = W + (size_t)(gate * HDIM + bx * 8 + g) * HDIM + c * 16;

    uint2 o;
    o.x = packh2(row[2 * tg],     row[2 * tg + 1]);
    o.y = packh2(row[2 * tg + 8], row[2 * tg + 9]);
    out[idx] = o;
}

__global__ void transpose1024(const float* __restrict__ in, float* __restrict__ out)
{
    __shared__ float t[32][33];
    int x = blockIdx.x * 32 + threadIdx.x;
    int y0 = blockIdx.y * 32;
    for (int r = threadIdx.y; r < 32; r += 8)
        t[r][threadIdx.x] = in[(size_t)(y0 + r) * HDIM + x];
    __syncthreads();
    int xo = blockIdx.y * 32 + threadIdx.x;
    for (int r = threadIdx.y; r < 32; r += 8)
        out[(size_t)(blockIdx.x * 32 + r) * HDIM + xo] = t[threadIdx.x][r];
}

// ----------------------------- tf32 mma GEMM (unchanged, proven) -------------
template <bool BIAS>
__global__ void __launch_bounds__(256) gemm_tf32(
    const float* __restrict__ A, const float* __restrict__ Bw,
    const float* __restrict__ bias, float* __restrict__ C,
    int M, int N, int K)
{
    __shared__ uint32_t As[32][132];
    __shared__ uint32_t Bs[32][132];

    const int tid = threadIdx.x;
    const int lane = tid & 31, wid = tid >> 5;
    const int g = lane >> 2, tg = lane & 3;
    const int wm = (wid & 3) * 32;
    const int wn = (wid >> 2) * 64;
    const int m0 = blockIdx.y * 128, n0 = blockIdx.x * 128;

    float acc[2][8][4];
#pragma unroll
    for (int a = 0; a < 2; a++)
#pragma unroll
        for (int b = 0; b < 8; b++)
#pragma unroll
            for (int c = 0; c < 4; c++) acc[a][b][c] = 0.f;

    for (int k0 = 0; k0 < K; k0 += 32) {
#pragma unroll
        for (int r = 0; r < 4; r++) {
            int idx = tid + r * 256;
            int row = idx >> 3, kq = (idx & 7) * 4;
            float4 av = *(const float4*)&A[(size_t)(m0 + row) * K + k0 + kq];
            As[kq + 0][row] = f2tf32(av.x);
            As[kq + 1][row] = f2tf32(av.y);
            As[kq + 2][row] = f2tf32(av.z);
            As[kq + 3][row] = f2tf32(av.w);
            float4 bv = *(const float4*)&Bw[(size_t)(n0 + row) * K + k0 + kq];
            Bs[kq + 0][row] = f2tf32(bv.x);
            Bs[kq + 1][row] = f2tf32(bv.y);
            Bs[kq + 2][row] = f2tf32(bv.z);
            Bs[kq + 3][row] = f2tf32(bv.w);
        }
        __syncthreads();
#pragma unroll
        for (int kk = 0; kk < 32; kk += 8) {
            uint32_t af[2][4], bf[8][2];
#pragma unroll
            for (int mt = 0; mt < 2; mt++) {
                af[mt][0] = As[kk + tg][wm + mt * 16 + g];
                af[mt][1] = As[kk + tg][wm + mt * 16 + g + 8];
                af[mt][2] = As[kk + tg + 4][wm + mt * 16 + g];
                af[mt][3] = As[kk + tg + 4][wm + mt * 16 + g + 8];
            }
#pragma unroll
            for (int nt = 0; nt < 8; nt++) {
                bf[nt][0] = Bs[kk + tg][wn + nt * 8 + g];
                bf[nt][1] = Bs[kk + tg + 4][wn + nt * 8 + g];
            }
#pragma unroll
            for (int mt = 0; mt < 2; mt++)
#pragma unroll
                for (int nt = 0; nt < 8; nt++)
                    mma_tf32(acc[mt][nt], af[mt], bf[nt]);
        }
        __syncthreads();
    }

#pragma unroll
    for (int mt = 0; mt < 2; mt++) {
#pragma unroll
        for (int nt = 0; nt < 8; nt++) {
            int row = m0 + wm + mt * 16 + g;
            int col = n0 + wn + nt * 8 + 2 * tg;
            float b0 = BIAS ? bias[col] : 0.f;
            float b1 = BIAS ? bias[col + 1] : 0.f;
            C[(size_t)row * N + col]       = acc[mt][nt][0] + b0;
            C[(size_t)row * N + col + 1]   = acc[mt][nt][1] + b1;
            C[(size_t)(row + 8) * N + col]     = acc[mt][nt][2] + b0;
            C[(size_t)(row + 8) * N + col + 1] = acc[mt][nt][3] + b1;
        }
    }
}

// ----------------------------- persistent GRU scan ---------------------------
// 128 blocks x 256 thr. Block owns 8 h-cols; warp owns 16 batch rows.
// A (h hi/lo fp16 fragments) streamed via cp.async.bulk into double-buffered
// 64KB smem windows; W fp16 single-plane fragments resident in 48KB smem;
// h_prev in registers. 2 MMAs per (chunk, gate).
// dyn smem: Wsm uint2[6144] (48KB) | Abuf uint4[2*4096] (128KB) | mbar[2]
#define SMEM_BYTES (49152 + 131072 + 64)

__global__ void __launch_bounds__(256) gru_scan_persistent(
    const float* __restrict__ gates_p, const float* __restrict__ gates_h,
    const uint4* __restrict__ Wf,      // [2][WF16_U4_PER] slabs
    const float* __restrict__ pbhh, const float* __restrict__ hbhh,
    float* __restrict__ op, float* __restrict__ hbuf, uint4* __restrict__ Hf)
{
    extern __shared__ uint4 sm4[];
    uint2* Wsm2 = (uint2*)sm4;            // 6144 uint2 (48KB)
    uint4* Abuf = sm4 + WF16_U4_PER;      // 2 x 4096 uint4

    const int tid = threadIdx.x, lane = tid & 31, wid = tid >> 5;
    const int g = lane >> 2, tg = lane & 3;
    const int bx = blockIdx.x;
    const int hc = bx * 8;

    const uint32_t smem_base = (uint32_t)__cvta_generic_to_shared(sm4);
    const uint32_t abase     = smem_base + 49152;
    const uint32_t mb0       = smem_base + 49152 + 131072;
    const uint32_t mb1       = mb0 + 8;

    const unsigned rel0 = *(volatile unsigned*)&g_release;

    if (tid == 0) {
        mbar_init(mb0, 1);
        mbar_init(mb1, 1);
        asm volatile("fence.proxy.async.shared::cta;" ::: "memory");
    }

    // premise W slab -> smem
    {
        const uint4* src = Wf + (size_t)bx * WF16_U4_PER;
        for (int i = tid; i < WF16_U4_PER; i += 256) sm4[i] = src[i];
    }
    __syncthreads();

    float hreg[4] = {0.f, 0.f, 0.f, 0.f};   // (i,jj): b=16*wid+g+8i, col=hc+2tg+jj
    float bR[2], bZ[2], bN[2];
    {
        int c0 = hc + 2 * tg;
        bR[0] = pbhh[c0];            bR[1] = pbhh[c0 + 1];
        bZ[0] = pbhh[HDIM + c0];     bZ[1] = pbhh[HDIM + c0 + 1];
        bN[0] = pbhh[2 * HDIM + c0]; bN[1] = pbhh[2 * HDIM + c0 + 1];
    }

    // producer store indices (SoA layout, identical to R10)
    const int pc  = bx >> 1;            // chunk this block's 8 cols live in
    const int pj  = (bx & 1) * 2;       // a-reg word base (0 or 2)
    uint32_t* HfW = (uint32_t*)Hf;

    for (int s = 0; s < 256; s++) {
        const bool prem = s < 128;
        const int t = s & 127;

        if (s == 128) {
            const uint4* src = Wf + ((size_t)128 + bx) * WF16_U4_PER;
            for (int i = tid; i < WF16_U4_PER; i += 256) sm4[i] = src[i];
            __syncthreads();
            int c0 = hc + 2 * tg;
            bR[0] = hbhh[c0];            bR[1] = hbhh[c0 + 1];
            bZ[0] = hbhh[HDIM + c0];     bZ[1] = hbhh[HDIM + c0 + 1];
            bN[0] = hbhh[2 * HDIM + c0]; bN[1] = hbhh[2 * HDIM + c0 + 1];
        }

        const float* gx = prem ? gates_p : gates_h;

        // prefetch gx (independent of h)
        float gxr[3][4];
#pragma unroll
        for (int i = 0; i < 2; i++) {
            int b = wid * 16 + g + 8 * i;
            size_t base = ((size_t)b * TDIM + t) * G3 + hc + 2 * tg;
#pragma unroll
            for (int jj = 0; jj < 2; jj++) {
                gxr[0][i * 2 + jj] = __ldg(&gx[base + jj]);
                gxr[1][i * 2 + jj] = __ldg(&gx[base + HDIM + jj]);
                gxr[2][i * 2 + jj] = __ldg(&gx[base + 2 * HDIM + jj]);
            }
        }

        float acc[3][4];
#pragma unroll
        for (int a = 0; a < 3; a++)
#pragma unroll
            for (int c = 0; c < 4; c++) acc[a][c] = 0.f;

        if (s > 0) {
            const int par = (s - 1) & 1;
            const char* src = (const char*)(Hf + (size_t)par * 64 * 512);

            // prologue: window 0
            if (tid == 0) {
                mbar_expect(mb0, 65536u);
                bulk_g2s(abase, src, 65536u, mb0);
            }

            for (int w = 0; w < 8; w++) {
                if (w >= 1) __syncthreads();   // buffer (w+1)&1 free (window w-1 done)
                if (w + 1 < 8 && tid == 0) {
                    uint32_t mbn = ((w + 1) & 1) ? mb1 : mb0;
                    bulk_g2s(abase + ((w + 1) & 1) * 65536u,
                             src + (size_t)(w + 1) * 65536u, 65536u, mbn);
                    mbar_expect(mbn, 65536u);
                }
                mbar_wait((w & 1) ? mb1 : mb0, (w >> 1) & 1);

                const uint4* Aw = Abuf + (w & 1) * 4096;
                const int abh = wid * 32 + lane;           // hi uint4 idx in chunk
#pragma unroll
                for (int cc = 0; cc < 8; cc++) {
                    const int c = w * 8 + cc;
                    uint4 Ahi = Aw[cc * 512 + abh];
                    uint4 Alo = Aw[cc * 512 + 256 + abh];
                    const uint32_t* ah = (const uint32_t*)&Ahi;
                    const uint32_t* al = (const uint32_t*)&Alo;
#pragma unroll
                    for (int gt = 0; gt < 3; gt++) {
                        uint2 w2 = Wsm2[(c * 3 + gt) * 32 + lane];
                        mma_f16(acc[gt], ah, w2.x, w2.y);
                        mma_f16(acc[gt], al, w2.x, w2.y);
                    }
                }
            }
        }

        // epilogue
        const int par_o = s & 1;
        const size_t cbase = ((size_t)par_o * 64 + pc) * 512;   // chunk base (uint4)
#pragma unroll
        for (int i = 0; i < 2; i++) {
            int b = wid * 16 + g + 8 * i;
            float h0, h1;
#pragma unroll
            for (int jj = 0; jj < 2; jj++) {
                int ai = i * 2 + jj;
                float r = sigmoidf_(gxr[0][ai] + acc[0][ai] + bR[jj]);
                float z = sigmoidf_(gxr[1][ai] + acc[1][ai] + bZ[jj]);
                float n = tanhf(gxr[2][ai] + r * (acc[2][ai] + bN[jj]));
                float h = (1.f - z) * n + z * hreg[ai];
                hreg[ai] = h;
                if (jj == 0) h0 = h; else h1 = h;
            }
            if (prem) {
                float* dst = op + (size_t)t * BH + (size_t)b * HDIM + hc + 2 * tg;
                dst[0] = h0; dst[1] = h1;
            } else if (s == 255) {
                float* dst = hbuf + (size_t)b * HDIM + hc + 2 * tg;
                dst[0] = h0; dst[1] = h1;
            }
            // fp16 hi/lo fragment stores (SoA): hi at cbase + wid*32+lane, lo +256
            __half q0 = __float2half_rn(h0), q1 = __float2half_rn(h1);
            uint32_t hiw = (uint32_t)*(uint16_t*)&q0 | ((uint32_t)*(uint16_t*)&q1 << 16);
            uint32_t low = packh2(h0 - __half2float(q0), h1 - __half2float(q1));
            HfW[(cbase + wid * 32 + lane) * 4 + pj + i]       = hiw;
            HfW[(cbase + 256 + wid * 32 + lane) * 4 + pj + i] = low;
        }

        // grid barrier (tight spin)
        __threadfence();
        __syncthreads();
        if (tid == 0) {
            unsigned r = atomicAdd(&g_arrive, 1u);
            if ((r & 127u) == 127u) atomicAdd(&g_release, 1u);
            while ((unsigned)(*(volatile unsigned*)&g_release - rel0) < (unsigned)(s + 1)) { }
            __threadfence();
        }
        __syncthreads();
    }
}

// ----------------------------- fp32 GEMM for small matmuls -------------------
template <bool TRANSB, bool BIAS>
__global__ void gemm_tiled(const float* __restrict__ A, const float* __restrict__ Bm,
                           const float* __restrict__ bias, float* __restrict__ C,
                           int M, int N, int K)
{
    __shared__ float As[8][132];
    __shared__ float Bs[8][132];

    const int tid = threadIdx.x;
    const int tx = tid & 15, ty = tid >> 4;
    const int m0 = blockIdx.y * 128, n0 = blockIdx.x * 128;

    float acc[8][8];
#pragma unroll
    for (int i = 0; i < 8; i++)
#pragma unroll
        for (int j = 0; j < 8; j++) acc[i][j] = 0.f;

    const int a_row = tid >> 1;
    const int a_k4  = (tid & 1) * 4;
    const int b_kr  = tid >> 5;
    const int b_n4  = (tid & 31) * 4;

    for (int k0 = 0; k0 < K; k0 += 8) {
        float4 av = *(const float4*)&A[(size_t)(m0 + a_row) * K + k0 + a_k4];
        As[a_k4 + 0][a_row] = av.x;
        As[a_k4 + 1][a_row] = av.y;
        As[a_k4 + 2][a_row] = av.z;
        As[a_k4 + 3][a_row] = av.w;
        if (TRANSB) {
            float4 bv = *(const float4*)&Bm[(size_t)(n0 + a_row) * K + k0 + a_k4];
            Bs[a_k4 + 0][a_row] = bv.x;
            Bs[a_k4 + 1][a_row] = bv.y;
            Bs[a_k4 + 2][a_row] = bv.z;
            Bs[a_k4 + 3][a_row] = bv.w;
        } else {
            float4 bv = *(const float4*)&Bm[(size_t)(k0 + b_kr) * N + n0 + b_n4];
            Bs[b_kr][b_n4 + 0] = bv.x;
            Bs[b_kr][b_n4 + 1] = bv.y;
            Bs[b_kr][b_n4 + 2] = bv.z;
            Bs[b_kr][b_n4 + 3] = bv.w;
        }
        __syncthreads();
#pragma unroll
        for (int kk = 0; kk < 8; kk++) {
            float a[8], b[8];
#pragma unroll
            for (int i = 0; i < 8; i++) a[i] = As[kk][ty + 16 * i];
#pragma unroll
            for (int j = 0; j < 8; j++) b[j] = Bs[kk][tx + 16 * j];
#pragma unroll
            for (int i = 0; i < 8; i++)
#pragma unroll
                for (int j = 0; j < 8; j++) acc[i][j] += a[i] * b[j];
        }
        __syncthreads();
    }

#pragma unroll
    for (int i = 0; i < 8; i++) {
        int m = m0 + ty + 16 * i;
#pragma unroll
        for (int j = 0; j < 8; j++) {
            int n = n0 + tx + 16 * j;
            float v = acc[i][j];
            if (BIAS) v += bias[n];
            C[(size_t)m * N + n] = v;
        }
    }
}

// ----------------------------- attention -------------------------------------
__global__ void attn_kernel(const float* __restrict__ WyM, const float* __restrict__ Wh,
                            const float* __restrict__ Walpha, const float* __restrict__ op,
                            float* __restrict__ rout)
{
    __shared__ float sc[128];
    __shared__ float red[256];
    const int b = blockIdx.x;
    const int tid = threadIdx.x;
    const int lane = tid & 31;
    const int warp = tid >> 5;

    for (int t = warp; t < TDIM; t += 8) {
        const float* wy = WyM + ((size_t)t * BDIM + b) * HDIM;
        const float* wh = Wh + (size_t)b * HDIM;
        float s = 0.f;
        for (int d = lane; d < HDIM; d += 32)
            s += tanhf(wy[d] + wh[d]) * Walpha[d];
#pragma unroll
        for (int o = 16; o > 0; o >>= 1) s += __shfl_xor_sync(0xffffffffu, s, o);
        if (lane == 0) sc[t] = s;
    }
    __syncthreads();

    float v = (tid < 128) ? sc[tid] : -INFINITY;
    red[tid] = v;
    __syncthreads();
    for (int s = 128; s > 0; s >>= 1) {
        if (tid < s) red[tid] = fmaxf(red[tid], red[tid + s]);
        __syncthreads();
    }
    float mx = red[0];
    __syncthreads();
    float e = (tid < 128) ? expf(sc[tid] - mx) : 0.f;
    red[tid] = e;
    __syncthreads();
    for (int s = 128; s > 0; s >>= 1) {
        if (tid < s) red[tid] += red[tid + s];
        __syncthreads();
    }
    float sum = red[0];
    __syncthreads();
    if (tid < 128) sc[tid] = e / sum;
    __syncthreads();

    for (int h = tid; h < HDIM; h += 256) {
        float acc = 0.f;
        for (int t = 0; t < TDIM; t++)
            acc += sc[t] * op[((size_t)t * BDIM + b) * HDIM + h];
        rout[(size_t)b * HDIM + h] = acc;
    }
}

__global__ void combine_tanh(const float* __restrict__ a, const float* __restrict__ b,
                             float* __restrict__ c, int n)
{
    int i = blockIdx.x * blockDim.x + threadIdx.x;
    if (i < n) c[i] = tanhf(a[i] + b[i]);
}

__global__ void final_kernel(const float* __restrict__ hstar, const float* __restrict__ outw,
                             const float* __restrict__ outb, float* __restrict__ out)
{
    __shared__ float red[128];
    __shared__ float lg[3];
    const int b = blockIdx.x;
    const int tid = threadIdx.x;

    for (int c = 0; c < 3; c++) {
        float p = 0.f;
        for (int h = tid; h < HDIM; h += 128)
            p += hstar[(size_t)b * HDIM + h] * outw[(size_t)c * HDIM + h];
        red[tid] = p;
        __syncthreads();
        for (int s = 64; s > 0; s >>= 1) {
            if (tid < s) red[tid] += red[tid + s];
            __syncthreads();
        }
        if (tid == 0) lg[c] = tanhf(red[0] + outb[c]);
        __syncthreads();
    }
    if (tid == 0) {
        float m = fmaxf(lg[0], fmaxf(lg[1], lg[2]));
        float s = expf(lg[0] - m) + expf(lg[1] - m) + expf(lg[2] - m);
        float lse = logf(s);
        for (int c = 0; c < 3; c++) out[b * 3 + c] = lg[c] - m - lse;
    }
}

// ----------------------------- launch ----------------------------------------
extern "C" void kernel_launch(void* const* d_in, const int* in_sizes, int n_in,
                              void* d_out, int out_size)
{
    const float* premise    = (const float*)d_in[0];
    const float* hypothesis = (const float*)d_in[1];
    const float* p_Wih = (const float*)d_in[2];
    const float* p_Whh = (const float*)d_in[3];
    const float* p_bih = (const float*)d_in[4];
    const float* p_bhh = (const float*)d_in[5];
    const float* h_Wih = (const float*)d_in[6];
    const float* h_Whh = (const float*)d_in[7];
    const float* h_bih = (const float*)d_in[8];
    const float* h_bhh = (const float*)d_in[9];
    const float* W_y     = (const float*)d_in[10];
    const float* W_h     = (const float*)d_in[11];
    const float* W_alpha = (const float*)d_in[12];
    const float* W_x     = (const float*)d_in[13];
    const float* W_p     = (const float*)d_in[14];
    const float* out_w   = (const float*)d_in[15];
    const float* out_b   = (const float*)d_in[16];

    float *gates_p, *gates_h, *op, *hbuf, *WyT, *WyM, *Whs, *rs, *G1, *G2, *hstar;
    uint4 *Wf, *Hf;
    cudaGetSymbolAddress((void**)&gates_p, g_gates_p);
    cudaGetSymbolAddress((void**)&gates_h, g_gates_h);
    cudaGetSymbolAddress((void**)&op,      g_op);
    cudaGetSymbolAddress((void**)&hbuf,    g_hbuf);
    cudaGetSymbolAddress((void**)&Wf,      g_Wf16);
    cudaGetSymbolAddress((void**)&Hf,      g_Hf);
    cudaGetSymbolAddress((void**)&WyT,     g_WyT);
    cudaGetSymbolAddress((void**)&WyM,     g_WyM);
    cudaGetSymbolAddress((void**)&Whs,     g_Wh);
    cudaGetSymbolAddress((void**)&rs,      g_r);
    cudaGetSymbolAddress((void**)&G1,      g_G1);
    cudaGetSymbolAddress((void**)&G2,      g_G2);
    cudaGetSymbolAddress((void**)&hstar,   g_hstar);

    const int MB = TDIM * BDIM;

    // prep
    {
        int n = 2 * 128 * WF16_U2_PER;
        pack_w_f16<<<(n + 255) / 256, 256>>>(p_Whh, h_Whh, (uint2*)Wf);
    }
    transpose1024<<<dim3(32, 32), dim3(32, 8)>>>(W_y, WyT);

    // input-gate GEMMs
    gemm_tf32<true><<<dim3(G3 / 128, MB / 128), 256>>>(
        premise, p_Wih, p_bih, gates_p, MB, G3, HDIM);
    gemm_tf32<true><<<dim3(G3 / 128, MB / 128), 256>>>(
        hypothesis, h_Wih, h_bih, gates_h, MB, G3, HDIM);

    // persistent scan
    static bool attr_set = false;
    if (!attr_set) {
        cudaFuncSetAttribute(gru_scan_persistent,
                             cudaFuncAttributeMaxDynamicSharedMemorySize,
                             SMEM_BYTES);
        attr_set = true;
    }
    gru_scan_persistent<<<128, 256, SMEM_BYTES>>>(
        gates_p, gates_h, Wf, p_bhh, h_bhh, op, hbuf, Hf);

    // attention
    gemm_tf32<false><<<dim3(HDIM / 128, MB / 128), 256>>>(
        op, WyT, nullptr, WyM, MB, HDIM, HDIM);
    gemm_tiled<false, false><<<dim3(HDIM / 128, 1), 256>>>(
        hbuf, W_h, nullptr, Whs, BDIM, HDIM, HDIM);
    attn_kernel<<<128, 256>>>(WyM, Whs, W_alpha, op, rs);

    // h_star and classifier
    gemm_tiled<false, false><<<dim3(HDIM / 128, 1), 256>>>(
        rs, W_p, nullptr, G1, BDIM, HDIM, HDIM);
    gemm_tiled<false, false><<<dim3(HDIM / 128, 1), 256>>>(
        hbuf, W_x, nullptr, G2, BDIM, HDIM, HDIM);
    combine_tanh<<<(BH + 255) / 256, 256>>>(G1, G2, hstar, BH);
    final_kernel<<<128, 128>>>(hstar, out_w, out_b, (float*)d_out);
}